// round 2
// baseline (speedup 1.0000x reference)
#include <cuda_runtime.h>
#include <cstdint>

#define NNODES 100000
#define NEDGES 640000
#define FIN 128
#define FOUT 64
#define BN_EPS 1e-5f

// ---------------- scratch (static device globals; no runtime allocation) ----
__device__ float g_h[(size_t)NNODES * FIN];     // x @ W_gcn
__device__ float g_agg[(size_t)NNODES * FIN];   // aggregated messages
__device__ float g_t[(size_t)NNODES * FOUT];    // hidden after GEMM2
__device__ float g_deg[NNODES];
__device__ float g_dinv[NNODES];
__device__ float g_sum1[FIN], g_sq1[FIN], g_a1[FIN], g_c1[FIN];
__device__ float g_sum2[FOUT], g_sq2[FOUT], g_a2[FOUT], g_c2[FOUT];

// ---------------- zero deg + stats ------------------------------------------
__global__ void zero_kernel(int M) {
    int i = blockIdx.x * blockDim.x + threadIdx.x;
    for (int j = i; j < M; j += gridDim.x * blockDim.x) g_deg[j] = 0.f;
    if (i < FIN)  { g_sum1[i] = 0.f; g_sq1[i] = 0.f; }
    if (i < FOUT) { g_sum2[i] = 0.f; g_sq2[i] = 0.f; }
}

// ---------------- degree -----------------------------------------------------
__global__ void deg_kernel(const int* __restrict__ dst, int E, int M) {
    int e = blockIdx.x * blockDim.x + threadIdx.x;
    if (e < E) {
        int d = dst[e];
        if ((unsigned)d < (unsigned)M) atomicAdd(&g_deg[d], 1.0f);
    }
}

__global__ void dinv_kernel(int M) {
    int i = blockIdx.x * blockDim.x + threadIdx.x;
    if (i < M) g_dinv[i] = rsqrtf(g_deg[i] + 1.0f);  // +1 = self loop
}

// ---------------- self-loop init of agg: agg[i] = h[i] * dinv[i]^2 ----------
__global__ void init_agg_kernel(int M) {
    const int V = FIN / 4;
    long long total = (long long)M * V;
    long long stride = (long long)gridDim.x * blockDim.x;
    for (long long i = blockIdx.x * (long long)blockDim.x + threadIdx.x; i < total; i += stride) {
        int row = (int)(i / V);
        float w = g_dinv[row]; w *= w;
        float4 v = ((const float4*)g_h)[i];
        v.x *= w; v.y *= w; v.z *= w; v.w *= w;
        ((float4*)g_agg)[i] = v;
    }
}

// ---------------- edge scatter: agg[d] += h[s] * dinv[s]*dinv[d] ------------
// one warp per edge; each lane: one float4 load + 4 atomicAdds (REDG, no return)
__global__ void scatter_kernel(const int* __restrict__ src, const int* __restrict__ dst,
                               int E, int M) {
    int warp = (blockIdx.x * blockDim.x + threadIdx.x) >> 5;
    int lane = threadIdx.x & 31;
    if (warp >= E) return;
    int s = src[warp];
    int d = dst[warp];
    if ((unsigned)s >= (unsigned)M || (unsigned)d >= (unsigned)M) return;
    float w = g_dinv[s] * g_dinv[d];
    float4 v = *(const float4*)&g_h[(size_t)s * FIN + lane * 4];
    float* p = &g_agg[(size_t)d * FIN + lane * 4];
    atomicAdd(p + 0, v.x * w);
    atomicAdd(p + 1, v.y * w);
    atomicAdd(p + 2, v.z * w);
    atomicAdd(p + 3, v.w * w);
}

// ---------------- per-column sum / sumsq ------------------------------------
template <int F>
__global__ void stats_kernel(const float* __restrict__ X, int M,
                             float* __restrict__ sum, float* __restrict__ sq) {
    constexpr int RP = 256 / F;
    int col  = threadIdx.x % F;
    int rsub = threadIdx.x / F;
    float s = 0.f, q = 0.f;
    for (int r = blockIdx.x * RP + rsub; r < M; r += gridDim.x * RP) {
        float v = X[(size_t)r * F + col];
        s += v; q += v * v;
    }
    __shared__ float sh[256];
    sh[threadIdx.x] = s; __syncthreads();
    if (rsub == 0) {
        #pragma unroll
        for (int k = 1; k < RP; k++) s += sh[k * F + col];
    }
    __syncthreads();
    sh[threadIdx.x] = q; __syncthreads();
    if (rsub == 0) {
        #pragma unroll
        for (int k = 1; k < RP; k++) q += sh[k * F + col];
        atomicAdd(&sum[col], s);
        atomicAdd(&sq[col],  q);
    }
}

template <int F>
__global__ void finalize_kernel(const float* __restrict__ sum, const float* __restrict__ sq,
                                const float* __restrict__ gamma, const float* __restrict__ beta,
                                int M, float* __restrict__ a, float* __restrict__ c) {
    int i = threadIdx.x;
    if (i < F) {
        float mean = sum[i] / (float)M;
        float var  = sq[i] / (float)M - mean * mean;
        float s = gamma[i] * rsqrtf(var + BN_EPS);
        a[i] = s;
        c[i] = beta[i] - mean * s;
    }
}

// ---------------- SGEMM with optional fused BN+ReLU on input, bias on output
// C[M,N] = act(A) [M,K] @ B [K,N]; act = relu(a*x+c) per K-column when BNIN
template <int N, int K, bool BNIN, bool BIAS>
__global__ __launch_bounds__(256) void sgemm_kernel(
    const float* __restrict__ A, const float* __restrict__ B, float* __restrict__ C,
    int M, const float* __restrict__ sc, const float* __restrict__ shf,
    const float* __restrict__ bias) {
    constexpr int BM = 128, BK = 8, TM = 8, TN = N / 16;
    __shared__ float As[BK][BM + 4];
    __shared__ float Bs[BK][N];
    __shared__ float s_sc[K], s_sh[K];

    int tid = threadIdx.x;
    if (BNIN) {
        for (int i = tid; i < K; i += 256) { s_sc[i] = sc[i]; s_sh[i] = shf[i]; }
    }
    __syncthreads();

    int tx = tid & 15, ty = tid >> 4;
    int row0 = blockIdx.x * BM;

    float acc[TM][TN];
    #pragma unroll
    for (int i = 0; i < TM; i++)
        #pragma unroll
        for (int j = 0; j < TN; j++) acc[i][j] = 0.f;

    int ar = tid >> 1;
    int ak = (tid & 1) * 4;
    int arow = row0 + ar;
    bool avalid = (arow < M);

    for (int k0 = 0; k0 < K; k0 += BK) {
        float4 av = make_float4(0.f, 0.f, 0.f, 0.f);
        if (avalid) av = *(const float4*)&A[(size_t)arow * K + k0 + ak];
        if (BNIN) {
            av.x = fmaxf(fmaf(av.x, s_sc[k0 + ak + 0], s_sh[k0 + ak + 0]), 0.f);
            av.y = fmaxf(fmaf(av.y, s_sc[k0 + ak + 1], s_sh[k0 + ak + 1]), 0.f);
            av.z = fmaxf(fmaf(av.z, s_sc[k0 + ak + 2], s_sh[k0 + ak + 2]), 0.f);
            av.w = fmaxf(fmaf(av.w, s_sc[k0 + ak + 3], s_sh[k0 + ak + 3]), 0.f);
        }
        As[ak + 0][ar] = av.x; As[ak + 1][ar] = av.y;
        As[ak + 2][ar] = av.z; As[ak + 3][ar] = av.w;

        #pragma unroll
        for (int i = tid; i < BK * N / 4; i += 256) {
            int kr = i / (N / 4);
            int c4 = (i % (N / 4)) * 4;
            *(float4*)&Bs[kr][c4] = *(const float4*)&B[(size_t)(k0 + kr) * N + c4];
        }
        __syncthreads();

        #pragma unroll
        for (int kk = 0; kk < BK; kk++) {
            float a[TM], b[TN];
            *(float4*)&a[0] = *(const float4*)&As[kk][ty * TM];
            *(float4*)&a[4] = *(const float4*)&As[kk][ty * TM + 4];
            #pragma unroll
            for (int j = 0; j < TN; j += 4)
                *(float4*)&b[j] = *(const float4*)&Bs[kk][tx * TN + j];
            #pragma unroll
            for (int i = 0; i < TM; i++)
                #pragma unroll
                for (int j = 0; j < TN; j++)
                    acc[i][j] = fmaf(a[i], b[j], acc[i][j]);
        }
        __syncthreads();
    }

    float bj[TN];
    if (BIAS) {
        #pragma unroll
        for (int j = 0; j < TN; j++) bj[j] = bias[tx * TN + j];
    }
    #pragma unroll
    for (int i = 0; i < TM; i++) {
        int grow = row0 + ty * TM + i;
        if (grow < M) {
            #pragma unroll
            for (int j = 0; j < TN; j += 4) {
                float4 v;
                v.x = acc[i][j]; v.y = acc[i][j + 1];
                v.z = acc[i][j + 2]; v.w = acc[i][j + 3];
                if (BIAS) { v.x += bj[j]; v.y += bj[j + 1]; v.z += bj[j + 2]; v.w += bj[j + 3]; }
                *(float4*)&C[(size_t)grow * N + tx * TN + j] = v;
            }
        }
    }
}

// ---------------- launch ----------------------------------------------------
extern "C" void kernel_launch(void* const* d_in, const int* in_sizes, int n_in,
                              void* d_out, int out_size) {
    const float* x     = (const float*)d_in[0];
    const int*   ei    = (const int*)d_in[1];
    const float* W_gcn = (const float*)d_in[2];
    // d_in[3] = b_gcn : exactly absorbed by BN1 (mean-subtraction) -> unused
    const float* bn_g  = (const float*)d_in[4];
    const float* bn_b  = (const float*)d_in[5];
    const float* W1    = (const float*)d_in[6];
    // d_in[7] = b1    : exactly absorbed by BN2 -> unused
    const float* mg    = (const float*)d_in[8];
    const float* mb    = (const float*)d_in[9];
    const float* W2    = (const float*)d_in[10];
    const float* b2    = (const float*)d_in[11];
    float* out = (float*)d_out;

    int M = in_sizes[0] / FIN;
    int E = in_sizes[1] / 2;
    const int* src = ei;
    const int* dst = ei + E;

    void *p_h, *p_agg, *p_t, *p_sum1, *p_sq1, *p_a1, *p_c1, *p_sum2, *p_sq2, *p_a2, *p_c2;
    cudaGetSymbolAddress(&p_h, g_h);
    cudaGetSymbolAddress(&p_agg, g_agg);
    cudaGetSymbolAddress(&p_t, g_t);
    cudaGetSymbolAddress(&p_sum1, g_sum1);
    cudaGetSymbolAddress(&p_sq1, g_sq1);
    cudaGetSymbolAddress(&p_a1, g_a1);
    cudaGetSymbolAddress(&p_c1, g_c1);
    cudaGetSymbolAddress(&p_sum2, g_sum2);
    cudaGetSymbolAddress(&p_sq2, g_sq2);
    cudaGetSymbolAddress(&p_a2, g_a2);
    cudaGetSymbolAddress(&p_c2, g_c2);

    zero_kernel<<<256, 256>>>(M);
    deg_kernel<<<(E + 255) / 256, 256>>>(dst, E, M);
    dinv_kernel<<<(M + 255) / 256, 256>>>(M);

    // GEMM1: h = x @ W_gcn
    sgemm_kernel<FIN, FIN, false, false><<<(M + 127) / 128, 256>>>(
        x, W_gcn, (float*)p_h, M, nullptr, nullptr, nullptr);

    init_agg_kernel<<<12500, 256>>>(M);
    scatter_kernel<<<(E + 7) / 8, 256>>>(src, dst, E, M);

    // BN1 stats
    stats_kernel<FIN><<<1024, 256>>>((const float*)p_agg, M, (float*)p_sum1, (float*)p_sq1);
    finalize_kernel<FIN><<<1, 128>>>((const float*)p_sum1, (const float*)p_sq1,
                                     bn_g, bn_b, M, (float*)p_a1, (float*)p_c1);

    // GEMM2: t = relu(BN1(agg)) @ W1   (b1 absorbed by BN2)
    sgemm_kernel<FOUT, FIN, true, false><<<(M + 127) / 128, 256>>>(
        (const float*)p_agg, W1, (float*)p_t, M,
        (const float*)p_a1, (const float*)p_c1, nullptr);

    // BN2 stats
    stats_kernel<FOUT><<<1024, 256>>>((const float*)p_t, M, (float*)p_sum2, (float*)p_sq2);
    finalize_kernel<FOUT><<<1, 64>>>((const float*)p_sum2, (const float*)p_sq2,
                                     mg, mb, M, (float*)p_a2, (float*)p_c2);

    // GEMM3: out = relu(BN2(t)) @ W2 + b2
    sgemm_kernel<FOUT, FOUT, true, true><<<(M + 127) / 128, 256>>>(
        (const float*)p_t, W2, out, M,
        (const float*)p_a2, (const float*)p_c2, b2);
}

// round 4
// speedup vs baseline: 1.4514x; 1.4514x over previous
#include <cuda_runtime.h>
#include <cstdint>

#define NNODES 100000
#define NEDGES 640000
#define FIN 128
#define FOUT 64
#define BN_EPS 1e-5f
#define SCAN_BS 256
#define MAX_BLOCKS 512   // ceil(NNODES/SCAN_BS) = 391 < 512

// ---------------- scratch (static device globals; no runtime allocation) ----
__device__ float g_h[(size_t)NNODES * FIN];     // x @ W_gcn
__device__ float g_agg[(size_t)NNODES * FIN];   // aggregated messages
__device__ float g_t[(size_t)NNODES * FOUT];    // hidden after GEMM2
__device__ int   g_degi[NNODES];
__device__ float g_dinv[NNODES];
__device__ int   g_off[NNODES + 1];
__device__ int   g_cursor[NNODES];
__device__ int   g_bsum[MAX_BLOCKS];
__device__ int   g_boff[MAX_BLOCKS];
__device__ int   g_elist[NEDGES];
__device__ float g_sum1[FIN], g_sq1[FIN], g_a1[FIN], g_c1[FIN];
__device__ float g_sum2[FOUT], g_sq2[FOUT], g_a2[FOUT], g_c2[FOUT];

// ---------------- zero ------------------------------------------------------
__global__ void zero_kernel(int M) {
    int i = blockIdx.x * blockDim.x + threadIdx.x;
    for (int j = i; j < M; j += gridDim.x * blockDim.x) g_degi[j] = 0;
    if (i < FIN)  { g_sum1[i] = 0.f; g_sq1[i] = 0.f; }
    if (i < FOUT) { g_sum2[i] = 0.f; g_sq2[i] = 0.f; }
}

// ---------------- in-degree count -------------------------------------------
__global__ void deg_kernel(const int* __restrict__ dst, int E, int M) {
    int e = blockIdx.x * blockDim.x + threadIdx.x;
    if (e < E) {
        int d = dst[e];
        if ((unsigned)d < (unsigned)M) atomicAdd(&g_degi[d], 1);
    }
}

__global__ void dinv_kernel(int M) {
    int i = blockIdx.x * blockDim.x + threadIdx.x;
    if (i < M) g_dinv[i] = rsqrtf((float)g_degi[i] + 1.0f);  // +1 = self loop
}

// ---------------- prefix scan (3 kernels) -----------------------------------
__global__ void scan1_kernel(int M) {
    __shared__ int sh[SCAN_BS];
    int i = blockIdx.x * SCAN_BS + threadIdx.x;
    int v = (i < M) ? g_degi[i] : 0;
    sh[threadIdx.x] = v;
    __syncthreads();
    #pragma unroll
    for (int ofs = 1; ofs < SCAN_BS; ofs <<= 1) {
        int t = 0;
        if (threadIdx.x >= ofs) t = sh[threadIdx.x - ofs];
        __syncthreads();
        sh[threadIdx.x] += t;
        __syncthreads();
    }
    if (i < M) g_off[i] = sh[threadIdx.x] - v;          // exclusive within block
    if (threadIdx.x == SCAN_BS - 1) g_bsum[blockIdx.x] = sh[SCAN_BS - 1];
}

__global__ void scan2_kernel(int NB) {
    __shared__ int sh[MAX_BLOCKS];
    int t = threadIdx.x;
    int v = (t < NB) ? g_bsum[t] : 0;
    sh[t] = v;
    __syncthreads();
    #pragma unroll
    for (int ofs = 1; ofs < MAX_BLOCKS; ofs <<= 1) {
        int u = 0;
        if (t >= ofs) u = sh[t - ofs];
        __syncthreads();
        sh[t] += u;
        __syncthreads();
    }
    if (t < NB) g_boff[t] = sh[t] - v;                   // exclusive block offset
}

__global__ void scan3_kernel(int M, int E) {
    int i = blockIdx.x * blockDim.x + threadIdx.x;
    if (i < M) {
        int o = g_off[i] + g_boff[i / SCAN_BS];
        g_off[i] = o;
        g_cursor[i] = o;
    }
    if (i == 0) g_off[M] = E;  // upper bound (out-of-range dst never counted/filled)
}

// note: g_off[M] is set to E assuming all dst valid; if some were dropped,
// last node's range still ends at total filled count stored via cursor —
// we instead read range end from off[d+1] for d<M-1 and cursor-consistency
// holds because fill only appends within counted slots.

// ---------------- edge-list fill --------------------------------------------
__global__ void fill_kernel(const int* __restrict__ src, const int* __restrict__ dst,
                            int E, int M) {
    int e = blockIdx.x * blockDim.x + threadIdx.x;
    if (e < E) {
        int s = src[e];
        int d = dst[e];
        if ((unsigned)s < (unsigned)M && (unsigned)d < (unsigned)M) {
            int p = atomicAdd(&g_cursor[d], 1);
            g_elist[p] = s;
        }
    }
}

// ---------------- gather: agg[d] = dinv[d]*sum(dinv[s]*h[s]) + dinv[d]^2*h[d]
// one warp per node; lane l covers feature columns 4l..4l+3
__global__ void gather_kernel(int M) {
    int warp = (blockIdx.x * blockDim.x + threadIdx.x) >> 5;
    int lane = threadIdx.x & 31;
    if (warp >= M) return;
    int d = warp;
    int e0 = g_off[d];
    int e1 = g_cursor[d];     // cursor ended exactly at the count filled for d
    float4 acc = make_float4(0.f, 0.f, 0.f, 0.f);
    for (int e = e0; e < e1; e++) {
        int s = g_elist[e];                 // broadcast across warp
        float ws = g_dinv[s];               // broadcast
        float4 v = *(const float4*)&g_h[(size_t)s * FIN + lane * 4];
        acc.x = fmaf(v.x, ws, acc.x);
        acc.y = fmaf(v.y, ws, acc.y);
        acc.z = fmaf(v.z, ws, acc.z);
        acc.w = fmaf(v.w, ws, acc.w);
    }
    float wd = g_dinv[d];
    float4 vs = *(const float4*)&g_h[(size_t)d * FIN + lane * 4];
    float4 o;
    o.x = wd * acc.x + wd * wd * vs.x;
    o.y = wd * acc.y + wd * wd * vs.y;
    o.z = wd * acc.z + wd * wd * vs.z;
    o.w = wd * acc.w + wd * wd * vs.w;
    *(float4*)&g_agg[(size_t)d * FIN + lane * 4] = o;
}

// ---------------- per-column sum / sumsq ------------------------------------
template <int F>
__global__ void stats_kernel(const float* __restrict__ X, int M,
                             float* __restrict__ sum, float* __restrict__ sq) {
    constexpr int RP = 256 / F;
    int col  = threadIdx.x % F;
    int rsub = threadIdx.x / F;
    float s = 0.f, q = 0.f;
    for (int r = blockIdx.x * RP + rsub; r < M; r += gridDim.x * RP) {
        float v = X[(size_t)r * F + col];
        s += v; q += v * v;
    }
    __shared__ float sh[256];
    sh[threadIdx.x] = s; __syncthreads();
    if (rsub == 0) {
        #pragma unroll
        for (int k = 1; k < RP; k++) s += sh[k * F + col];
    }
    __syncthreads();
    sh[threadIdx.x] = q; __syncthreads();
    if (rsub == 0) {
        #pragma unroll
        for (int k = 1; k < RP; k++) q += sh[k * F + col];
        atomicAdd(&sum[col], s);
        atomicAdd(&sq[col],  q);
    }
}

template <int F>
__global__ void finalize_kernel(const float* __restrict__ sum, const float* __restrict__ sq,
                                const float* __restrict__ gamma, const float* __restrict__ beta,
                                int M, float* __restrict__ a, float* __restrict__ c) {
    int i = threadIdx.x;
    if (i < F) {
        float mean = sum[i] / (float)M;
        float var  = sq[i] / (float)M - mean * mean;
        float s = gamma[i] * rsqrtf(var + BN_EPS);
        a[i] = s;
        c[i] = beta[i] - mean * s;
    }
}

// ---------------- SGEMM with optional fused BN+ReLU on input, bias on output
template <int N, int K, bool BNIN, bool BIAS>
__global__ __launch_bounds__(256) void sgemm_kernel(
    const float* __restrict__ A, const float* __restrict__ B, float* __restrict__ C,
    int M, const float* __restrict__ sc, const float* __restrict__ shf,
    const float* __restrict__ bias) {
    constexpr int BM = 128, BK = 8, TM = 8, TN = N / 16;
    __shared__ float As[BK][BM + 4];
    __shared__ float Bs[BK][N];
    __shared__ float s_sc[K], s_sh[K];

    int tid = threadIdx.x;
    if (BNIN) {
        for (int i = tid; i < K; i += 256) { s_sc[i] = sc[i]; s_sh[i] = shf[i]; }
    }
    __syncthreads();

    int tx = tid & 15, ty = tid >> 4;
    int row0 = blockIdx.x * BM;

    float acc[TM][TN];
    #pragma unroll
    for (int i = 0; i < TM; i++)
        #pragma unroll
        for (int j = 0; j < TN; j++) acc[i][j] = 0.f;

    int ar = tid >> 1;
    int ak = (tid & 1) * 4;
    int arow = row0 + ar;
    bool avalid = (arow < M);

    for (int k0 = 0; k0 < K; k0 += BK) {
        float4 av = make_float4(0.f, 0.f, 0.f, 0.f);
        if (avalid) av = *(const float4*)&A[(size_t)arow * K + k0 + ak];
        if (BNIN) {
            av.x = fmaxf(fmaf(av.x, s_sc[k0 + ak + 0], s_sh[k0 + ak + 0]), 0.f);
            av.y = fmaxf(fmaf(av.y, s_sc[k0 + ak + 1], s_sh[k0 + ak + 1]), 0.f);
            av.z = fmaxf(fmaf(av.z, s_sc[k0 + ak + 2], s_sh[k0 + ak + 2]), 0.f);
            av.w = fmaxf(fmaf(av.w, s_sc[k0 + ak + 3], s_sh[k0 + ak + 3]), 0.f);
        }
        As[ak + 0][ar] = av.x; As[ak + 1][ar] = av.y;
        As[ak + 2][ar] = av.z; As[ak + 3][ar] = av.w;

        #pragma unroll
        for (int i = tid; i < BK * N / 4; i += 256) {
            int kr = i / (N / 4);
            int c4 = (i % (N / 4)) * 4;
            *(float4*)&Bs[kr][c4] = *(const float4*)&B[(size_t)(k0 + kr) * N + c4];
        }
        __syncthreads();

        #pragma unroll
        for (int kk = 0; kk < BK; kk++) {
            float a[TM], b[TN];
            *(float4*)&a[0] = *(const float4*)&As[kk][ty * TM];
            *(float4*)&a[4] = *(const float4*)&As[kk][ty * TM + 4];
            #pragma unroll
            for (int j = 0; j < TN; j += 4)
                *(float4*)&b[j] = *(const float4*)&Bs[kk][tx * TN + j];
            #pragma unroll
            for (int i = 0; i < TM; i++)
                #pragma unroll
                for (int j = 0; j < TN; j++)
                    acc[i][j] = fmaf(a[i], b[j], acc[i][j]);
        }
        __syncthreads();
    }

    float bj[TN];
    if (BIAS) {
        #pragma unroll
        for (int j = 0; j < TN; j++) bj[j] = bias[tx * TN + j];
    }
    #pragma unroll
    for (int i = 0; i < TM; i++) {
        int grow = row0 + ty * TM + i;
        if (grow < M) {
            #pragma unroll
            for (int j = 0; j < TN; j += 4) {
                float4 v;
                v.x = acc[i][j]; v.y = acc[i][j + 1];
                v.z = acc[i][j + 2]; v.w = acc[i][j + 3];
                if (BIAS) { v.x += bj[j]; v.y += bj[j + 1]; v.z += bj[j + 2]; v.w += bj[j + 3]; }
                *(float4*)&C[(size_t)grow * N + tx * TN + j] = v;
            }
        }
    }
}

// ---------------- launch ----------------------------------------------------
extern "C" void kernel_launch(void* const* d_in, const int* in_sizes, int n_in,
                              void* d_out, int out_size) {
    const float* x     = (const float*)d_in[0];
    const int*   ei    = (const int*)d_in[1];
    const float* W_gcn = (const float*)d_in[2];
    // d_in[3] = b_gcn : exactly absorbed by BN1 (mean-subtraction) -> unused
    const float* bn_g  = (const float*)d_in[4];
    const float* bn_b  = (const float*)d_in[5];
    const float* W1    = (const float*)d_in[6];
    // d_in[7] = b1    : exactly absorbed by BN2 -> unused
    const float* mg    = (const float*)d_in[8];
    const float* mb    = (const float*)d_in[9];
    const float* W2    = (const float*)d_in[10];
    const float* b2    = (const float*)d_in[11];
    float* out = (float*)d_out;

    int M = in_sizes[0] / FIN;
    int E = in_sizes[1] / 2;
    const int* src = ei;
    const int* dst = ei + E;
    int NB = (M + SCAN_BS - 1) / SCAN_BS;

    void *p_h, *p_agg, *p_t, *p_sum1, *p_sq1, *p_a1, *p_c1, *p_sum2, *p_sq2, *p_a2, *p_c2;
    cudaGetSymbolAddress(&p_h, g_h);
    cudaGetSymbolAddress(&p_agg, g_agg);
    cudaGetSymbolAddress(&p_t, g_t);
    cudaGetSymbolAddress(&p_sum1, g_sum1);
    cudaGetSymbolAddress(&p_sq1, g_sq1);
    cudaGetSymbolAddress(&p_a1, g_a1);
    cudaGetSymbolAddress(&p_c1, g_c1);
    cudaGetSymbolAddress(&p_sum2, g_sum2);
    cudaGetSymbolAddress(&p_sq2, g_sq2);
    cudaGetSymbolAddress(&p_a2, g_a2);
    cudaGetSymbolAddress(&p_c2, g_c2);

    // index machinery (overlappable cheap kernels)
    zero_kernel<<<256, 256>>>(M);
    deg_kernel<<<(E + 255) / 256, 256>>>(dst, E, M);
    dinv_kernel<<<(M + 255) / 256, 256>>>(M);
    scan1_kernel<<<NB, SCAN_BS>>>(M);
    scan2_kernel<<<1, MAX_BLOCKS>>>(NB);
    scan3_kernel<<<NB, SCAN_BS>>>(M, E);
    fill_kernel<<<(E + 255) / 256, 256>>>(src, dst, E, M);

    // GEMM1: h = x @ W_gcn
    sgemm_kernel<FIN, FIN, false, false><<<(M + 127) / 128, 256>>>(
        x, W_gcn, (float*)p_h, M, nullptr, nullptr, nullptr);

    // CSR gather (replaces atomic scatter + init_agg)
    gather_kernel<<<(M * 32 + 255) / 256, 256>>>(M);

    // BN1 stats
    stats_kernel<FIN><<<1024, 256>>>((const float*)p_agg, M, (float*)p_sum1, (float*)p_sq1);
    finalize_kernel<FIN><<<1, 128>>>((const float*)p_sum1, (const float*)p_sq1,
                                     bn_g, bn_b, M, (float*)p_a1, (float*)p_c1);

    // GEMM2: t = relu(BN1(agg)) @ W1   (b1 absorbed by BN2)
    sgemm_kernel<FOUT, FIN, true, false><<<(M + 127) / 128, 256>>>(
        (const float*)p_agg, W1, (float*)p_t, M,
        (const float*)p_a1, (const float*)p_c1, nullptr);

    // BN2 stats
    stats_kernel<FOUT><<<1024, 256>>>((const float*)p_t, M, (float*)p_sum2, (float*)p_sq2);
    finalize_kernel<FOUT><<<1, 64>>>((const float*)p_sum2, (const float*)p_sq2,
                                     mg, mb, M, (float*)p_a2, (float*)p_c2);

    // GEMM3: out = relu(BN2(t)) @ W2 + b2
    sgemm_kernel<FOUT, FOUT, true, true><<<(M + 127) / 128, 256>>>(
        (const float*)p_t, W2, out, M,
        (const float*)p_a2, (const float*)p_c2, b2);
}